// round 17
// baseline (speedup 1.0000x reference)
#include <cuda_runtime.h>
#include <cuda_bf16.h>
#include <cuda_fp16.h>

// Problem dims
#define SL 512
#define NB 64
#define NE 256
#define NH 256
#define NG 1024
#define NT 32

// ---------------------------------------------------------------------------
// Packed f32x2 helpers (emis)
// ---------------------------------------------------------------------------
#define FMA2(acc, a, b) \
    asm("fma.rn.f32x2 %0, %1, %2, %0;" : "+l"(acc) : "l"(a), "l"(b))
#define ADD2(acc, v) \
    asm("add.rn.f32x2 %0, %0, %1;" : "+l"(acc) : "l"(v))
#define UNPK2(lo, hi, v) do { unsigned _a, _b; \
    asm("mov.b64 {%0, %1}, %2;" : "=r"(_a), "=r"(_b) : "l"(v)); \
    lo = __uint_as_float(_a); hi = __uint_as_float(_b); } while (0)
#define TANHA(d, x) asm("tanh.approx.f32 %0, %1;" : "=f"(d) : "f"(x))
#define H2F2(d, h2u) do { __half2 _h = *(__half2*)&(h2u); \
    float2 _f = __half22float2(_h); \
    asm("mov.b64 %0, {%1, %2};" : "=l"(d) : "f"(_f.x), "f"(_f.y)); } while (0)

// fp16 tensor-core mma: D(16x8,f32) += A(16x16,f16,row) * B(16x8,f16,col)
__device__ __forceinline__ void mma16816(
    float& c0, float& c1, float& c2, float& c3,
    unsigned a0, unsigned a1, unsigned a2, unsigned a3,
    unsigned b0, unsigned b1)
{
    asm volatile(
        "mma.sync.aligned.m16n8k16.row.col.f32.f16.f16.f32 "
        "{%0,%1,%2,%3}, {%4,%5,%6,%7}, {%8,%9}, {%0,%1,%2,%3};"
        : "+f"(c0), "+f"(c1), "+f"(c2), "+f"(c3)
        : "r"(a0), "r"(a1), "r"(a2), "r"(a3), "r"(b0), "r"(b1));
}

// ---------------------------------------------------------------------------
// Device-global scratch.
// ---------------------------------------------------------------------------
__device__ __half    g_xproj[2][(size_t)SL * NB * NG];   // gate-last [l][b][h][g]
__device__ __half    g_hout [2][(size_t)SL * NB * NH];
__device__ float     g_em   [(size_t)SL * NB * NT];
__device__ __half    g_hbuf [2][2][NB * NH];             // fp16 h broadcast
__device__ float     g_WoutT[512 * NT];
__device__ float     g_llh  [NB];
__device__ __half    g_Wih16[2][NG * NE];    // fp16 W_ih, gate-last rows
__device__ __half    g_Whh16[2][NG * NH];    // fp16 W_hh, gate-last rows
__device__ float     g_bias_gl[2][NG];
__device__ unsigned  g_flag[8][32];          // 8 groups x 8 subs (padded rows)

// ---------------------------------------------------------------------------
// Kernel 0: prep — fp16 gate-last W_ih & W_hh, fused bias, W_out^T.
// grid = 4096 x 256
// ---------------------------------------------------------------------------
__global__ void wprep_kernel(
    const float* __restrict__ Wf, const float* __restrict__ Wb,
    const float* __restrict__ Whf, const float* __restrict__ Whb,
    const float* __restrict__ bihf, const float* __restrict__ bhhf,
    const float* __restrict__ bihb, const float* __restrict__ bhhb,
    const float* __restrict__ Wout)
{
    int idx = blockIdx.x * 256 + threadIdx.x;      // 0..1048575
    if (idx < 524288) {
        int k = idx & 255, n = (idx >> 8) & 1023, dir = idx >> 18;
        const float* W = dir ? Wb : Wf;
        int wrow = (n & 3) * 256 + (n >> 2);
        g_Wih16[dir][n * 256 + k] = __float2half_rn(W[wrow * 256 + k]);
    } else {
        int j = idx - 524288;
        int k = j & 255, n = (j >> 8) & 1023, dir = j >> 18;
        const float* W = dir ? Whb : Whf;
        int wrow = (n & 3) * 256 + (n >> 2);
        g_Whh16[dir][n * 256 + k] = __float2half_rn(W[wrow * 256 + k]);
    }
    if (idx < 2048) {
        int dir = idx >> 10, n = idx & 1023;
        int wrow = (n & 3) * 256 + (n >> 2);
        g_bias_gl[dir][n] = dir ? (bihb[wrow] + bhhb[wrow])
                                : (bihf[wrow] + bhhf[wrow]);
    }
    if (idx < 512 * 32) {
        int k = idx >> 5, t = idx & 31;
        g_WoutT[idx] = Wout[t * 512 + k];
    }
}

// ---------------------------------------------------------------------------
// Kernel 1: x_proj via fp16 tensor cores (unchanged from passing R15).
// ---------------------------------------------------------------------------
#define APAD 264
#define XPM_SMEM (128 * APAD * 2 + 64 * APAD * 2 + 64 * 4)
__global__ __launch_bounds__(128) void xproj_kernel(
    const float* __restrict__ embed, const int* __restrict__ seqs)
{
    extern __shared__ __half xsm[];
    __half* As = xsm;
    __half* Ws = xsm + 128 * APAD;
    float*  bs = (float*)(xsm + 192 * APAD);

    const int tid  = threadIdx.x;
    const int bm   = blockIdx.x;
    const int dir  = blockIdx.y;
    const int w    = tid >> 5;
    const int lane = tid & 31;
    const int g8   = lane >> 2;
    const int tq   = lane & 3;
    const int mbase = w * 32;

    {
        const float* src = embed + (long)seqs[bm * 128 + tid] * 256;
        __half* dst = As + tid * APAD;
#pragma unroll
        for (int k = 0; k < 256; k += 8) {
            float4 v0 = __ldg((const float4*)(src + k));
            float4 v1 = __ldg((const float4*)(src + k + 4));
            uint4 pk;
            *(__half2*)&pk.x = __floats2half2_rn(v0.x, v0.y);
            *(__half2*)&pk.y = __floats2half2_rn(v0.z, v0.w);
            *(__half2*)&pk.z = __floats2half2_rn(v1.x, v1.y);
            *(__half2*)&pk.w = __floats2half2_rn(v1.z, v1.w);
            *(uint4*)(dst + k) = pk;
        }
    }
    __syncthreads();

    __half* outp = g_xproj[dir];
    const uint4* wsrc0 = (const uint4*)g_Wih16[dir];

    for (int nc = 0; nc < 16; nc++) {
        {
            const uint4* wsrc = wsrc0 + (size_t)nc * 64 * 32;
#pragma unroll
            for (int i = 0; i < 16; i++) {
                int idx = tid + i * 128;
                int n = idx >> 5, c = idx & 31;
                uint4 v = __ldg(wsrc + idx);
                *(uint4*)(Ws + n * APAD + c * 8) = v;
            }
            if (tid < 64) bs[tid] = g_bias_gl[dir][nc * 64 + tid];
        }
        __syncthreads();

        float C[2][8][4];
#pragma unroll
        for (int mt = 0; mt < 2; mt++)
#pragma unroll
            for (int nt = 0; nt < 8; nt++)
#pragma unroll
                for (int q = 0; q < 4; q++) C[mt][nt][q] = 0.f;

#pragma unroll
        for (int ks = 0; ks < 16; ks++) {
            const int kb = ks * 16 + tq * 2;
            unsigned a[2][4];
#pragma unroll
            for (int mt = 0; mt < 2; mt++) {
                const __half* ab = As + (mbase + mt * 16 + g8) * APAD;
                a[mt][0] = *(const unsigned*)(ab + kb);
                a[mt][1] = *(const unsigned*)(ab + 8 * APAD + kb);
                a[mt][2] = *(const unsigned*)(ab + kb + 8);
                a[mt][3] = *(const unsigned*)(ab + 8 * APAD + kb + 8);
            }
#pragma unroll
            for (int nt = 0; nt < 8; nt++) {
                const __half* bp = Ws + (nt * 8 + g8) * APAD;
                unsigned b0 = *(const unsigned*)(bp + kb);
                unsigned b1 = *(const unsigned*)(bp + kb + 8);
                mma16816(C[0][nt][0], C[0][nt][1], C[0][nt][2], C[0][nt][3],
                         a[0][0], a[0][1], a[0][2], a[0][3], b0, b1);
                mma16816(C[1][nt][0], C[1][nt][1], C[1][nt][2], C[1][nt][3],
                         a[1][0], a[1][1], a[1][2], a[1][3], b0, b1);
            }
        }

#pragma unroll
        for (int nt = 0; nt < 8; nt++) {
            const int ncol = nc * 64 + nt * 8 + tq * 2;
            const float bx = bs[nt * 8 + tq * 2];
            const float by = bs[nt * 8 + tq * 2 + 1];
#pragma unroll
            for (int mt = 0; mt < 2; mt++) {
                long r0 = (long)bm * 128 + mbase + mt * 16 + g8;
                __half2 h01 = __floats2half2_rn(C[mt][nt][0] + bx,
                                                C[mt][nt][1] + by);
                __half2 h23 = __floats2half2_rn(C[mt][nt][2] + bx,
                                                C[mt][nt][3] + by);
                *(__half2*)(outp + r0 * 1024 + ncol)       = h01;
                *(__half2*)(outp + (r0 + 8) * 1024 + ncol) = h23;
            }
        }
        __syncthreads();
    }
}

// ---------------------------------------------------------------------------
// Kernel 2: persistent BiLSTM via tensor cores.
// 64 blocks x 128 thr.  Block = 16 batch x 32 hidden (128 gate-last N cols).
// grp = dir*4 + batchgroup (8 groups x 8 blocks).  W_hh chunk fp16 in smem;
// h fp16 in g_hbuf consumed directly as mma A fragments.  No K-split.
// ---------------------------------------------------------------------------
#define LPAD 264
#define LSTM_SMEM ((128 * LPAD + 16 * LPAD) * 2)     // 76032 B
__global__ __launch_bounds__(128) void lstm_kernel(const int* __restrict__ masks)
{
    extern __shared__ __half lsm[];
    __half* Wsm = lsm;                 // [128 n][LPAD]
    __half* Asm = lsm + 128 * LPAD;    // [16 b][LPAD]

    const int tid  = threadIdx.x;
    const int lane = tid & 31;
    const int w    = tid >> 5;
    const int bid  = blockIdx.x;
    const int grp  = bid & 7;            // dir*4 + bgrp
    const int sub  = bid >> 3;           // 0..7 hidden chunk
    const int dir  = grp >> 2;
    const int b0   = (grp & 3) * 16;
    const int h0   = sub * 32;
    const int g8   = lane >> 2;
    const int tq   = lane & 3;
    const int ghalf = tq & 1;            // 0: gates i,f  1: gates g,o
    const int hoff  = tq >> 1;           // hidden parity within n8 tile

    const __half* xp = g_xproj[dir];
    __half* outp = g_hout[dir];

    const unsigned base = *(volatile unsigned*)&g_flag[grp][sub];

    // Load W_hh chunk: gate-last rows [h0*4, h0*4+128) x 256 k, fp16.
    {
        const uint4* wsrc = (const uint4*)(g_Whh16[dir] + (size_t)h0 * 4 * 256);
#pragma unroll
        for (int i = 0; i < 32; i++) {
            int idx = tid + i * 128;          // 0..4095
            int n = idx >> 5, c = idx & 31;
            uint4 v = __ldg(wsrc + idx);
            *(uint4*)(Wsm + n * LPAD + c * 8) = v;
        }
    }

    // Per-thread state: 4 (b,h) pairs (nt = 0..3).
    // b = b0 + g8 + (ghalf ? 8 : 0);  h = h0 + w*8 + nt*2 + hoff.
    const int bloc = g8 + (ghalf ? 8 : 0);
    const int bglob = b0 + bloc;
    float cst[4], hst[4];
#pragma unroll
    for (int nt = 0; nt < 4; nt++) { cst[nt] = 0.f; hst[nt] = 0.f; }

    // Publish initial h = 0 for this block's region (16 b x 32 h).
#pragma unroll
    for (int i = 0; i < 4; i++) {
        int idx = tid + i * 128;              // 0..511
        int r = idx >> 5, c = idx & 31;
        g_hbuf[dir][0][(b0 + r) * 256 + h0 + c] = __float2half_rn(0.f);
    }
    __threadfence();
    __syncthreads();
    if (tid == 0) *(volatile unsigned*)&g_flag[grp][sub] = base + 1u;

    // Prefetch x (4 gate-quads) + mask for step 0.
    const int l0 = dir ? 511 : 0;
    uint2 xr[4];
#pragma unroll
    for (int nt = 0; nt < 4; nt++) {
        int hg = h0 + w * 8 + nt * 2 + hoff;
        xr[nt] = __ldg((const uint2*)(xp + ((size_t)(l0 * 64 + bglob)) * 1024 + hg * 4));
    }
    int m = __ldg(masks + l0 * 64 + bglob);

    int p = 0;
    for (int step = 0; step < 512; step++) {
        const int l = dir ? (511 - step) : step;

        // Wait: 8 lanes poll the 8 peer flags in parallel.
        {
            const unsigned target = base + 1u + (unsigned)step;
            if (tid < 8) {
                volatile unsigned* f = &g_flag[grp][tid];
                while ((int)(*f - target) < 0) { }
            }
            __syncthreads();
        }

        // Stage h_prev (16 b x 256 h, fp16) from L2 into Asm.
        {
            const uint4* hb = (const uint4*)g_hbuf[dir][p];
#pragma unroll
            for (int i = 0; i < 4; i++) {
                int idx = tid + i * 128;      // 0..511
                int r = idx >> 5, c = idx & 31;
                uint4 v = __ldcg(hb + (b0 + r) * 32 + c);
                *(uint4*)(Asm + r * LPAD + c * 8) = v;
            }
        }
        __syncthreads();

        // GEMM: warp computes M=16 x N=32 (cols n = w*32 .. w*32+31), K=256.
        float C[4][4];
#pragma unroll
        for (int nt = 0; nt < 4; nt++)
#pragma unroll
            for (int q = 0; q < 4; q++) C[nt][q] = 0.f;

#pragma unroll
        for (int ks = 0; ks < 16; ks++) {
            const int kb = ks * 16 + tq * 2;
            const __half* ar = Asm + g8 * LPAD + kb;
            unsigned a0 = *(const unsigned*)ar;
            unsigned a1 = *(const unsigned*)(ar + 8 * LPAD);
            unsigned a2 = *(const unsigned*)(ar + 8);
            unsigned a3 = *(const unsigned*)(ar + 8 * LPAD + 8);
#pragma unroll
            for (int nt = 0; nt < 4; nt++) {
                const __half* bp = Wsm + (w * 32 + nt * 8 + g8) * LPAD + kb;
                unsigned b0r = *(const unsigned*)bp;
                unsigned b1r = *(const unsigned*)(bp + 8);
                mma16816(C[nt][0], C[nt][1], C[nt][2], C[nt][3],
                         a0, a1, a2, a3, b0r, b1r);
            }
        }

        // Gate exchange + update.  Even ghalf owns row g8; odd owns g8+8.
        __syncthreads();   // Asm reads done; safe to let next stores proceed later
#pragma unroll
        for (int nt = 0; nt < 4; nt++) {
            float r0 = __shfl_xor_sync(0xffffffffu, C[nt][0], 1);
            float r1 = __shfl_xor_sync(0xffffffffu, C[nt][1], 1);
            float r2 = __shfl_xor_sync(0xffffffffu, C[nt][2], 1);
            float r3 = __shfl_xor_sync(0xffffffffu, C[nt][3], 1);
            float pi, pf, pg, po;
            if (ghalf == 0) { pi = C[nt][0]; pf = C[nt][1]; pg = r0; po = r1; }
            else            { pi = r2;       pf = r3;       pg = C[nt][2]; po = C[nt][3]; }

            float2 x01 = __half22float2(*(__half2*)&xr[nt].x);
            float2 x23 = __half22float2(*(__half2*)&xr[nt].y);

            float ti, tf, tg, to;
            TANHA(ti, 0.5f * (x01.x + pi));
            TANHA(tf, 0.5f * (x01.y + pf));
            TANHA(tg, x23.x + pg);
            TANHA(to, 0.5f * (x23.y + po));
            float gi = fmaf(0.5f, ti, 0.5f);
            float gf = fmaf(0.5f, tf, 0.5f);
            float go = fmaf(0.5f, to, 0.5f);
            float cn = gf * cst[nt] + gi * tg;
            float tc; TANHA(tc, cn);
            float hn = go * tc;
            float outv;
            if (m) { cst[nt] = cn; hst[nt] = hn; outv = hn; } else { outv = 0.f; }

            int hg = h0 + w * 8 + nt * 2 + hoff;
            g_hbuf[dir][p ^ 1][bglob * 256 + hg] = __float2half_rn(hst[nt]);
            outp[((size_t)(l * 64 + bglob)) * 256 + hg] = __float2half_rn(outv);
        }

        __threadfence();
        __syncthreads();
        if (tid == 0)
            *(volatile unsigned*)&g_flag[grp][sub] = base + 2u + (unsigned)step;

        // Barrier shadow: next-step x/mask prefetch.
        const int sn = (step < 511) ? step + 1 : 511;
        const int ln = dir ? (511 - sn) : sn;
#pragma unroll
        for (int nt = 0; nt < 4; nt++) {
            int hg = h0 + w * 8 + nt * 2 + hoff;
            xr[nt] = __ldg((const uint2*)(xp + ((size_t)(ln * 64 + bglob)) * 1024 + hg * 4));
        }
        m = __ldg(masks + ln * 64 + bglob);

        p ^= 1;
    }
}

// ---------------------------------------------------------------------------
// Kernel 3: emissions (unchanged from passing R15 build).
// ---------------------------------------------------------------------------
#define WPADH 520
#define EMIS_SMEM_BYTES (32 * WPADH * 2 + 8 * 512 * 4)
__global__ __launch_bounds__(256) void emis_kernel(const float* __restrict__ bout)
{
    extern __shared__ char esm[];
    __half* wsmT = (__half*)esm;
    float*  hsm  = (float*)(esm + 32 * WPADH * 2);
    const int tid = threadIdx.x;
    const int r = tid >> 5, t = tid & 31;
    const float bb = bout[t];

    for (int i = 0; i < 64; i++) {
        int idx = tid + i * 256;
        int k = idx >> 5, tt = idx & 31;
        wsmT[tt * WPADH + k] = __float2half_rn(g_WoutT[idx]);
    }

    const uint4* h0p = (const uint4*)g_hout[0];
    const uint4* h1p = (const uint4*)g_hout[1];

    for (int it = 0; it < 4; it++) {
        const int bm = blockIdx.x * 4 + it;
        __syncthreads();
#pragma unroll
        for (int i = 0; i < 2; i++) {
            int s = tid + i * 256;
            int rr = s >> 6, c8 = s & 63;
            size_t row = (size_t)bm * 8 + rr;
            uint4 v = (c8 < 32) ? __ldg(h0p + row * 32 + c8)
                                : __ldg(h1p + row * 32 + (c8 - 32));
            int cb = (c8 < 32) ? c8 * 8 : 256 + (c8 - 32) * 8;
            float* dst = hsm + rr * 512 + cb;
            float2 f0 = __half22float2(*(__half2*)&v.x);
            float2 f1 = __half22float2(*(__half2*)&v.y);
            float2 f2 = __half22float2(*(__half2*)&v.z);
            float2 f3 = __half22float2(*(__half2*)&v.w);
            *(float4*)dst       = make_float4(f0.x, f0.y, f1.x, f1.y);
            *(float4*)(dst + 4) = make_float4(f2.x, f2.y, f3.x, f3.y);
        }
        __syncthreads();

        const float*  hr = hsm + r * 512;
        const __half* wrh = wsmT + t * WPADH;
        unsigned long long a0 = 0ull, a1 = 0ull, a2 = 0ull, a3 = 0ull;
#pragma unroll 4
        for (int k = 0; k < 512; k += 16) {
            ulonglong2 hA = *(const ulonglong2*)(hr + k);
            ulonglong2 hB = *(const ulonglong2*)(hr + k + 4);
            ulonglong2 hC = *(const ulonglong2*)(hr + k + 8);
            ulonglong2 hD = *(const ulonglong2*)(hr + k + 12);
            uint2 wA = *(const uint2*)(wrh + k);
            uint2 wB = *(const uint2*)(wrh + k + 4);
            uint2 wC = *(const uint2*)(wrh + k + 8);
            uint2 wD = *(const uint2*)(wrh + k + 12);
            unsigned long long w0, w1, w2, w3, w4, w5, w6, w7;
            H2F2(w0, wA.x); H2F2(w1, wA.y);
            H2F2(w2, wB.x); H2F2(w3, wB.y);
            H2F2(w4, wC.x); H2F2(w5, wC.y);
            H2F2(w6, wD.x); H2F2(w7, wD.y);
            FMA2(a0, hA.x, w0); FMA2(a0, hA.y, w1);
            FMA2(a1, hB.x, w2); FMA2(a1, hB.y, w3);
            FMA2(a2, hC.x, w4); FMA2(a2, hC.y, w5);
            FMA2(a3, hD.x, w6); FMA2(a3, hD.y, w7);
        }
        ADD2(a0, a1); ADD2(a2, a3); ADD2(a0, a2);
        float lo, hi;
        UNPK2(lo, hi, a0);
        g_em[((size_t)bm * 8 + r) * 32 + t] = lo + hi + bb;
    }
}

// ---------------------------------------------------------------------------
// Kernel 4: CRF (unchanged).
// ---------------------------------------------------------------------------
__global__ __launch_bounds__(128) void crf_kernel(
    const int* __restrict__ tags, const int* __restrict__ masks,
    const float* __restrict__ start_trans, const float* __restrict__ end_trans,
    const float* __restrict__ trans)
{
    __shared__ float tsm[NT * NT];
    __shared__ float ssm[NT];
    __shared__ float pm[4][NT];
    __shared__ float ps[4][NT];
    __shared__ float redf[8];
    __shared__ int   redi[8];

    const int b = blockIdx.x;
    const int tid = threadIdx.x;
    const int w = tid >> 5;
    const int j = tid & 31;

    for (int i = tid; i < NT * NT; i += 128) tsm[i] = trans[i];
    if (w == 0) ssm[j] = start_trans[j] + g_em[(size_t)b * 32 + j];
    __syncthreads();

    for (int l = 1; l < 512; l++) {
        float v[8];
        float mx = -3.4e38f;
#pragma unroll
        for (int ii = 0; ii < 8; ii++) {
            int i = w * 8 + ii;
            v[ii] = ssm[i] + tsm[i * 32 + j];
            mx = fmaxf(mx, v[ii]);
        }
        float s = 0.f;
#pragma unroll
        for (int ii = 0; ii < 8; ii++) s += __expf(v[ii] - mx);
        pm[w][j] = mx;
        ps[w][j] = s;
        __syncthreads();
        if (w == 0) {
            float m0 = pm[0][j], m1 = pm[1][j], m2 = pm[2][j], m3 = pm[3][j];
            float M = fmaxf(fmaxf(m0, m1), fmaxf(m2, m3));
            float S = ps[0][j] * __expf(m0 - M) + ps[1][j] * __expf(m1 - M)
                    + ps[2][j] * __expf(m2 - M) + ps[3][j] * __expf(m3 - M);
            float nxt = M + __logf(S) + g_em[((size_t)(l * 64 + b)) * 32 + j];
            if (masks[l * 64 + b]) ssm[j] = nxt;
        }
        __syncthreads();
    }

    float part = 0.f;
    int lenp = 0;
    for (int l = tid; l < 512; l += 128) {
        int m = masks[l * 64 + b];
        lenp += m;
        int tg = tags[l * 64 + b];
        float e = g_em[((size_t)(l * 64 + b)) * 32 + tg];
        if (l == 0) {
            part += start_trans[tg] + e;
        } else {
            int tp = tags[(l - 1) * 64 + b];
            part += (e + tsm[tp * 32 + tg]) * (float)m;
        }
    }
#pragma unroll
    for (int off = 16; off > 0; off >>= 1) {
        part += __shfl_xor_sync(0xffffffffu, part, off);
        lenp += __shfl_xor_sync(0xffffffffu, lenp, off);
    }
    if (j == 0) { redf[w] = part; redi[w] = lenp; }
    __syncthreads();

    if (w == 0) {
        float num_p = redf[0] + redf[1] + redf[2] + redf[3];
        int   length = redi[0] + redi[1] + redi[2] + redi[3];

        float tv = ssm[j] + end_trans[j];
        float mx = tv;
#pragma unroll
        for (int off = 16; off > 0; off >>= 1)
            mx = fmaxf(mx, __shfl_xor_sync(0xffffffffu, mx, off));
        float ex = __expf(tv - mx);
#pragma unroll
        for (int off = 16; off > 0; off >>= 1)
            ex += __shfl_xor_sync(0xffffffffu, ex, off);
        float logz = mx + __logf(ex);

        if (j == 0) {
            int last = tags[(length - 1) * 64 + b];
            g_llh[b] = (num_p + end_trans[last]) - logz;
        }
    }
}

// ---------------------------------------------------------------------------
// Kernel 5: out = -mean(llh)
// ---------------------------------------------------------------------------
__global__ void final_kernel(float* __restrict__ out) {
    if (threadIdx.x == 0) {
        float s = 0.f;
        for (int i = 0; i < NB; i++) s += g_llh[i];
        out[0] = -s / (float)NB;
    }
}

// ---------------------------------------------------------------------------
extern "C" void kernel_launch(void* const* d_in, const int* in_sizes, int n_in,
                              void* d_out, int out_size) {
    const int*   seqs        = (const int*)d_in[0];
    const int*   tags        = (const int*)d_in[1];
    const int*   masks       = (const int*)d_in[2];
    const float* embed       = (const float*)d_in[3];
    const float* W_ih_f      = (const float*)d_in[4];
    const float* W_hh_f      = (const float*)d_in[5];
    const float* b_ih_f      = (const float*)d_in[6];
    const float* b_hh_f      = (const float*)d_in[7];
    const float* W_ih_b      = (const float*)d_in[8];
    const float* W_hh_b      = (const float*)d_in[9];
    const float* b_ih_b      = (const float*)d_in[10];
    const float* b_hh_b      = (const float*)d_in[11];
    const float* W_out       = (const float*)d_in[12];
    const float* b_out       = (const float*)d_in[13];
    const float* start_trans = (const float*)d_in[14];
    const float* end_trans   = (const float*)d_in[15];
    const float* trans       = (const float*)d_in[16];

    cudaFuncSetAttribute(xproj_kernel, cudaFuncAttributeMaxDynamicSharedMemorySize,
                         XPM_SMEM);
    cudaFuncSetAttribute(lstm_kernel, cudaFuncAttributeMaxDynamicSharedMemorySize,
                         LSTM_SMEM);
    cudaFuncSetAttribute(emis_kernel, cudaFuncAttributeMaxDynamicSharedMemorySize,
                         EMIS_SMEM_BYTES);

    wprep_kernel<<<4096, 256>>>(W_ih_f, W_ih_b, W_hh_f, W_hh_b,
                                b_ih_f, b_hh_f, b_ih_b, b_hh_b, W_out);
    dim3 xg(256, 2);
    xproj_kernel<<<xg, 128, XPM_SMEM>>>(embed, seqs);
    lstm_kernel<<<64, 128, LSTM_SMEM>>>(masks);
    emis_kernel<<<1024, 256, EMIS_SMEM_BYTES>>>(b_out);
    crf_kernel<<<64, 128>>>(tags, masks, start_trans, end_trans, trans);
    final_kernel<<<1, 32>>>((float*)d_out);
}